// round 1
// baseline (speedup 1.0000x reference)
#include <cuda_runtime.h>
#include <cuda_bf16.h>

// YOLOv3 loss, sm_103a.
// Key insight: cls/reg losses only involve POSITIVE anchors (max IoU >= 0.5),
// so the 94MB predictions tensor is only gathered at positive rows (~1MB).
// Irreducible work = B*A*M IoU assignment (~220 MFLOP), latency-trivial.

#define NUM_CLASSES 80
#define MAXB 64
#define MAXM 64
#define IOU_THRESH 0.5f

__device__ float g_cls_sum[MAXB];
__device__ float g_reg_sum[MAXB];
__device__ float g_npos[MAXB];

__global__ void yolo_init_kernel(int B) {
    int i = threadIdx.x;
    if (i < B) {
        g_cls_sum[i] = 0.f;
        g_reg_sum[i] = 0.f;
        g_npos[i]    = 0.f;
    }
}

__device__ __forceinline__ float sigmoidf_fast(float x) {
    // saturates correctly for |x| large: __expf(+inf)->inf -> 0 ; __expf(-inf)->0 -> 1
    return 1.0f / (1.0f + __expf(-x));
}

__global__ void __launch_bounds__(256)
yolo_loss_kernel(const float* __restrict__ pred,
                 const float* __restrict__ ann,
                 const float* __restrict__ anchors,
                 int A, int M) {
    // Per-image box data staged in shared (M <= MAXM)
    __shared__ float s_x1[MAXM], s_y1[MAXM], s_x2[MAXM], s_y2[MAXM];
    __shared__ float s_area[MAXM], s_cx[MAXM], s_cy[MAXM];
    __shared__ float s_w[MAXM], s_h[MAXM], s_cl[MAXM];

    const int b = blockIdx.y;
    const float* annb = ann + (size_t)b * M * 5;
    for (int m = threadIdx.x; m < M; m += blockDim.x) {
        float x  = annb[m * 5 + 0];
        float y  = annb[m * 5 + 1];
        float w  = annb[m * 5 + 2];
        float h  = annb[m * 5 + 3];
        float cl = annb[m * 5 + 4];
        // reference: top-left -> center; corners are then (x, y, x+w, y+h)
        s_x1[m] = x;           s_y1[m] = y;
        s_x2[m] = x + w;       s_y2[m] = y + h;
        s_area[m] = w * h;
        s_cx[m] = x + 0.5f * w; s_cy[m] = y + 0.5f * h;
        s_w[m] = w;             s_h[m] = h;
        s_cl[m] = cl;
    }
    __syncthreads();

    const int a = blockIdx.x * blockDim.x + threadIdx.x;
    float clsc = 0.f, regc = 0.f, posc = 0.f;

    if (a < A) {
        const float ax = anchors[a * 4 + 0];
        const float ay = anchors[a * 4 + 1];
        const float aw = anchors[a * 4 + 2];
        const float ah = anchors[a * 4 + 3];
        const float ax1 = ax - 0.5f * aw, ay1 = ay - 0.5f * ah;
        const float ax2 = ax + 0.5f * aw, ay2 = ay + 0.5f * ah;
        const float areaA = aw * ah;

        // argmax over valid boxes; invalid boxes are -inf in the reference, so
        // skipping them while using strict '>' reproduces jnp.argmax exactly
        // (first occurrence of the max, idx 0 when nothing is valid).
        float best = -1.0f;
        int   bi   = 0;
        #pragma unroll 4
        for (int m = 0; m < M; m++) {
            if (s_cl[m] == -1.0f) continue;  // padded box
            float iw = fminf(ax2, s_x2[m]) - fmaxf(ax1, s_x1[m]);
            float ih = fminf(ay2, s_y2[m]) - fmaxf(ay1, s_y1[m]);
            iw = fmaxf(iw, 0.f);
            ih = fmaxf(ih, 0.f);
            float inter = iw * ih;
            float iou = inter / (areaA + s_area[m] - inter);
            if (iou > best) { best = iou; bi = m; }
        }

        if (best >= IOU_THRESH) {
            posc = 1.f;
            const float* row = pred + ((size_t)b * A + a) * (NUM_CLASSES + 5);

            // ---- regression term (sum of squared errors; divisions deferred) ----
            float r0 = row[0], r1 = row[1], r2 = row[2], r3 = row[3], r4 = row[4];
            float stx = sigmoidf_fast(s_cx[bi] - ax);
            float sty = sigmoidf_fast(s_cy[bi] - ay);
            float tw  = __logf(fmaxf(s_w[bi], 1.f) / aw);
            float th  = __logf(fmaxf(s_h[bi], 1.f) / ah);
            float d0 = sigmoidf_fast(r0) - stx;
            float d1 = sigmoidf_fast(r1) - sty;
            float d2 = r2 - tw;
            float d3 = r3 - th;
            float d4 = r4 - 1.0f;
            regc = d0*d0 + d1*d1 + d2*d2 + d3*d3 + d4*d4;

            // ---- classification BCE, collapsed one-hot form:
            // BCE = -( log p_t - log(1-p_t) + sum_c log(1-p_c) )
            float acc = 0.f;
            #pragma unroll 8
            for (int c = 0; c < NUM_CLASSES; c++) {
                acc += __logf(1.0f - row[5 + c]);
            }
            int t = (int)s_cl[bi];
            float pt = row[5 + t];
            clsc = -(__logf(pt) - __logf(1.0f - pt) + acc);
        }
    }

    // warp-level tree reduce, then one atomicAdd per warp (skipped if warp saw
    // no positive anchors — the overwhelmingly common case)
    const unsigned mask = 0xffffffffu;
    #pragma unroll
    for (int off = 16; off > 0; off >>= 1) {
        clsc += __shfl_down_sync(mask, clsc, off);
        regc += __shfl_down_sync(mask, regc, off);
        posc += __shfl_down_sync(mask, posc, off);
    }
    if ((threadIdx.x & 31) == 0 && posc > 0.f) {
        atomicAdd(&g_cls_sum[b], clsc);
        atomicAdd(&g_reg_sum[b], regc);
        atomicAdd(&g_npos[b],    posc);
    }
}

__global__ void yolo_finalize_kernel(float* __restrict__ out, int B) {
    // assumes B <= 32 (B = 16 here)
    int b = threadIdx.x;
    float cl = 0.f, rg = 0.f;
    if (b < B) {
        float n = g_npos[b];
        float denom = fmaxf(n, 1.f);
        cl = g_cls_sum[b] / denom;                       // (bce*posf).sum()/denom
        rg = (n > 0.f) ? g_reg_sum[b] / (denom * denom)  // (sum_sq/denom)/denom
                       : 0.f;
    }
    const unsigned mask = 0xffffffffu;
    #pragma unroll
    for (int off = 16; off > 0; off >>= 1) {
        cl += __shfl_down_sync(mask, cl, off);
        rg += __shfl_down_sync(mask, rg, off);
    }
    if (b == 0) {
        out[0] = cl / (float)B;
        out[1] = rg / (float)B;
    }
}

extern "C" void kernel_launch(void* const* d_in, const int* in_sizes, int n_in,
                              void* d_out, int out_size) {
    const float* pred    = (const float*)d_in[0];  // (B, NA, G, G, 5+C) f32
    const float* ann     = (const float*)d_in[1];  // (B, M, 5) f32
    const float* anchors = (const float*)d_in[2];  // (NA, G, G, 4) f32
    float* out = (float*)d_out;

    // derive shapes from element counts (C fixed at 80 for this problem)
    const int A = in_sizes[2] / 4;
    const int B = in_sizes[0] / (A * (NUM_CLASSES + 5));
    const int M = in_sizes[1] / (B * 5);

    yolo_init_kernel<<<1, 64>>>(B);

    dim3 grid((A + 255) / 256, B);
    yolo_loss_kernel<<<grid, 256>>>(pred, ann, anchors, A, M);

    yolo_finalize_kernel<<<1, 32>>>(out, B);
}

// round 2
// speedup vs baseline: 1.8501x; 1.8501x over previous
#include <cuda_runtime.h>
#include <cuda_bf16.h>

// YOLOv3 loss, sm_103a — single fused kernel.
// Positives-only evaluation (predictions gathered only at max-IoU>=0.5 rows),
// last-block finalize (threadfence + atomic counter) replaces init/finalize
// launches; accumulators self-reset each call so the CUDA graph replays
// deterministically.

#define NUM_CLASSES 80
#define MAXB 64
#define MAXM 64
#define IOU_THRESH 0.5f

__device__ float        g_cls_sum[MAXB];   // zero-initialized at module load
__device__ float        g_reg_sum[MAXB];
__device__ float        g_npos[MAXB];
__device__ unsigned int g_done;            // zero-initialized

__device__ __forceinline__ float sigmoidf_fast(float x) {
    return 1.0f / (1.0f + __expf(-x));
}

__global__ void __launch_bounds__(256)
yolo_loss_fused(const float* __restrict__ pred,
                const float* __restrict__ ann,
                const float* __restrict__ anchors,
                float* __restrict__ out,
                int A, int M, int B) {
    // compacted valid boxes (order-preserving -> jnp.argmax first-max semantics)
    __shared__ float4 s_corners[MAXM];               // x1,y1,x2,y2
    __shared__ float  s_area[MAXM];
    __shared__ float  s_cx[MAXM], s_cy[MAXM], s_w[MAXM], s_h[MAXM], s_cl[MAXM];
    __shared__ int    s_cnt;
    __shared__ int    s_last;

    const int b   = blockIdx.y;
    const int tid = threadIdx.x;

    // ---- warp 0: load + compact valid boxes (M <= 32) ----
    if (tid < 32) {
        int   m     = tid;
        bool  valid = false;
        float x = 0.f, y = 0.f, w = 0.f, h = 0.f, cl = -1.f;
        if (m < M) {
            const float* bm = ann + ((size_t)b * M + m) * 5;
            x = bm[0]; y = bm[1]; w = bm[2]; h = bm[3]; cl = bm[4];
            valid = (cl != -1.0f);
        }
        unsigned mask = __ballot_sync(0xffffffffu, valid);
        if (valid) {
            int slot = __popc(mask & ((1u << tid) - 1u));
            s_corners[slot] = make_float4(x, y, x + w, y + h);
            s_area[slot] = w * h;
            s_cx[slot] = x + 0.5f * w;
            s_cy[slot] = y + 0.5f * h;
            s_w[slot]  = w;
            s_h[slot]  = h;
            s_cl[slot] = cl;
        }
        if (tid == 0) s_cnt = __popc(mask);
    }
    __syncthreads();

    const int cnt = s_cnt;
    const int a   = blockIdx.x * blockDim.x + tid;
    float clsc = 0.f, regc = 0.f, posc = 0.f;

    if (a < A) {
        const float4 an = __ldg((const float4*)anchors + a);
        const float ax = an.x, ay = an.y, aw = an.z, ah = an.w;
        const float ax1 = ax - 0.5f * aw, ay1 = ay - 0.5f * ah;
        const float ax2 = ax + 0.5f * aw, ay2 = ay + 0.5f * ah;
        const float areaA = aw * ah;

        float best = -1.0f;
        int   bi   = 0;
        #pragma unroll 4
        for (int m = 0; m < cnt; m++) {
            float4 c = s_corners[m];
            float iw = fminf(ax2, c.z) - fmaxf(ax1, c.x);
            float ih = fminf(ay2, c.w) - fmaxf(ay1, c.y);
            iw = fmaxf(iw, 0.f);
            ih = fmaxf(ih, 0.f);
            float inter = iw * ih;
            float iou = __fdividef(inter, areaA + s_area[m] - inter);
            if (iou > best) { best = iou; bi = m; }
        }

        if (best >= IOU_THRESH) {
            posc = 1.f;
            const float* row = pred + ((size_t)b * A + a) * (NUM_CLASSES + 5);

            // regression: sum of squared errors (both /denom deferred)
            float r0 = row[0], r1 = row[1], r2 = row[2], r3 = row[3], r4 = row[4];
            float stx = sigmoidf_fast(s_cx[bi] - ax);
            float sty = sigmoidf_fast(s_cy[bi] - ay);
            float tw  = __logf(fmaxf(s_w[bi], 1.f) / aw);
            float th  = __logf(fmaxf(s_h[bi], 1.f) / ah);
            float d0 = sigmoidf_fast(r0) - stx;
            float d1 = sigmoidf_fast(r1) - sty;
            float d2 = r2 - tw;
            float d3 = r3 - th;
            float d4 = r4 - 1.0f;
            regc = d0*d0 + d1*d1 + d2*d2 + d3*d3 + d4*d4;

            // one-hot BCE collapsed: -( log p_t - log(1-p_t) + sum_c log(1-p_c) )
            float acc = 0.f;
            #pragma unroll 8
            for (int c = 0; c < NUM_CLASSES; c++)
                acc += __logf(1.0f - row[5 + c]);
            int t = (int)s_cl[bi];
            float pt = row[5 + t];
            clsc = -(__logf(pt) - __logf(1.0f - pt) + acc);
        }
    }

    // warp reduce, one conditional atomic per warp
    const unsigned full = 0xffffffffu;
    #pragma unroll
    for (int off = 16; off > 0; off >>= 1) {
        clsc += __shfl_down_sync(full, clsc, off);
        regc += __shfl_down_sync(full, regc, off);
        posc += __shfl_down_sync(full, posc, off);
    }
    if ((tid & 31) == 0 && posc > 0.f) {
        atomicAdd(&g_cls_sum[b], clsc);
        atomicAdd(&g_reg_sum[b], regc);
        atomicAdd(&g_npos[b],    posc);
    }

    // ---- last-block finalize ----
    __syncthreads();                 // all warps' atomics issued
    if (tid == 0) {
        __threadfence();             // make them visible before counter bump
        unsigned total = gridDim.x * gridDim.y;
        unsigned old = atomicAdd(&g_done, 1u);
        s_last = (old == total - 1u);
    }
    __syncthreads();

    if (s_last && tid < 32) {
        __threadfence();             // acquire other blocks' accumulator writes
        float cl = 0.f, rg = 0.f;
        if (tid < B) {
            float n = g_npos[tid];
            float denom = fmaxf(n, 1.f);
            cl = g_cls_sum[tid] / denom;
            rg = (n > 0.f) ? g_reg_sum[tid] / (denom * denom) : 0.f;
            // reset for the next graph replay
            g_cls_sum[tid] = 0.f;
            g_reg_sum[tid] = 0.f;
            g_npos[tid]    = 0.f;
        }
        #pragma unroll
        for (int off = 16; off > 0; off >>= 1) {
            cl += __shfl_down_sync(full, cl, off);
            rg += __shfl_down_sync(full, rg, off);
        }
        if (tid == 0) {
            out[0] = cl / (float)B;
            out[1] = rg / (float)B;
            g_done = 0u;             // reset counter for next replay
        }
    }
}

extern "C" void kernel_launch(void* const* d_in, const int* in_sizes, int n_in,
                              void* d_out, int out_size) {
    const float* pred    = (const float*)d_in[0];  // (B, A, 5+C) f32
    const float* ann     = (const float*)d_in[1];  // (B, M, 5) f32
    const float* anchors = (const float*)d_in[2];  // (A, 4) f32
    float* out = (float*)d_out;

    const int A = in_sizes[2] / 4;
    const int B = in_sizes[0] / (A * (NUM_CLASSES + 5));
    const int M = in_sizes[1] / (B * 5);

    dim3 grid((A + 255) / 256, B);
    yolo_loss_fused<<<grid, 256>>>(pred, ann, anchors, out, A, M, B);
}